// round 16
// baseline (speedup 1.0000x reference)
#include <cuda_runtime.h>
#include <cuda_fp16.h>
#include <cstdint>
#include <math.h>

#define Hd     1024
#define Bd     64
#define NDIM   5120
#define FOREST 255
#define KTOT   2048
#define PITCH  144                   // 64 fp16 = 128B + 16B pad (conflict-free)
#define SMEM_BARS 1024

// ---------------- static device scratch ----------------
__device__ __half g_Ah[(size_t)16384 * 2048];   // A fp16, row-major [row][k]
__device__ __half g_Wh[(size_t)5120 * 2048];    // W^T fp16, [n][k]
__device__ float g_bcat[NDIM];
__device__ __half g_pre[(size_t)8192 * NDIM];   // pre-activations, fp16
__device__ __half g_cbuf[2][(size_t)8192 * Hd]; // c ping-pong, fp16

// ---------------- helpers ----------------
__device__ __forceinline__ uint32_t smem_u32(const void* p) {
    uint32_t a;
    asm("{ .reg .u64 t; cvta.to.shared.u64 t, %1; cvt.u32.u64 %0, t; }" : "=r"(a) : "l"(p));
    return a;
}
__device__ __forceinline__ void cpasync16(uint32_t dst, const void* src) {
    asm volatile("cp.async.cg.shared.global [%0], [%1], 16;" :: "r"(dst), "l"(src));
}
__device__ __forceinline__ void mbar_init(uint32_t a, uint32_t c) {
    asm volatile("mbarrier.init.shared.b64 [%0], %1;" :: "r"(a), "r"(c) : "memory");
}
__device__ __forceinline__ void mbar_arrive(uint32_t a) {
    asm volatile("mbarrier.arrive.shared.b64 _, [%0];" :: "r"(a) : "memory");
}
__device__ __forceinline__ void cpasync_mbar_arrive(uint32_t a) {
    asm volatile("cp.async.mbarrier.arrive.noinc.shared.b64 [%0];" :: "r"(a) : "memory");
}
__device__ __forceinline__ void mbar_wait(uint32_t mbar, int phase) {
    asm volatile(
        "{\n\t.reg .pred P1;\n\t"
        "W_%=:\n\t"
        "mbarrier.try_wait.parity.acquire.cta.shared::cta.b64 P1, [%0], %1, 0x989680;\n\t"
        "@P1 bra.uni D_%=;\n\t"
        "bra.uni W_%=;\n\t"
        "D_%=:\n\t}"
        :: "r"(mbar), "r"(phase) : "memory");
}
__device__ __forceinline__ void ldsm4(uint32_t* r, uint32_t addr) {
    asm volatile("ldmatrix.sync.aligned.m8n8.x4.shared.b16 {%0,%1,%2,%3}, [%4];"
                 : "=r"(r[0]), "=r"(r[1]), "=r"(r[2]), "=r"(r[3]) : "r"(addr));
}
__device__ __forceinline__ void mma16816(float* c, const uint32_t* a, const uint32_t* b) {
    asm volatile("mma.sync.aligned.m16n8k16.row.col.f32.f16.f16.f32 "
                 "{%0,%1,%2,%3}, {%4,%5,%6,%7}, {%8,%9}, {%0,%1,%2,%3};"
                 : "+f"(c[0]), "+f"(c[1]), "+f"(c[2]), "+f"(c[3])
                 : "r"(a[0]), "r"(a[1]), "r"(a[2]), "r"(a[3]), "r"(b[0]), "r"(b[1]));
}
__device__ __forceinline__ uint32_t pk2h(__half a, __half b) {
    __half2 t(a, b);
    return *reinterpret_cast<uint32_t*>(&t);
}
__device__ __forceinline__ uint32_t pk2f(float a, float b) {
    return pk2h(__float2half_rn(a), __float2half_rn(b));
}
__device__ __forceinline__ uint4 cvt8h(const float* f) {
    uint32_t hw[4];
#pragma unroll
    for (int q = 0; q < 4; q++)
        hw[q] = pk2f(f[2*q], f[2*q+1]);
    return make_uint4(hw[0], hw[1], hw[2], hw[3]);
}
__device__ __forceinline__ void ld8h(const __half* p, float* f) {
    uint4 v = *(const uint4*)p;
    const __half2* h = (const __half2*)&v;
#pragma unroll
    for (int q = 0; q < 4; q++) {
        float2 t = __half22float2(h[q]);
        f[2*q] = t.x; f[2*q+1] = t.y;
    }
}
__device__ __forceinline__ float sigf(float x)   { return 1.0f / (1.0f + __expf(-x)); }
__device__ __forceinline__ float tanhf_(float x) { return 2.0f / (1.0f + __expf(-2.0f * x)) - 1.0f; }

// ---------------------------------------------------------------------------
// Weight pack with smem transpose: g_Wh[n][k] = fp16(cat(W;U)[k][n]).
// ---------------------------------------------------------------------------
__global__ __launch_bounds__(256)
void pack_w_kernel(const float* __restrict__ Wi, const float* __restrict__ Ui,
                   const float* __restrict__ Wfl, const float* __restrict__ Ufl,
                   const float* __restrict__ Wfr, const float* __restrict__ Ufr) {
    __shared__ float ts[64][65];
    int k0 = blockIdx.x * 64, n0 = blockIdx.y * 64;
    const float *Wm, *Um; int st, nc0;
    if (n0 < 3072)      { Wm = Wi;  Um = Ui;  st = 3072; nc0 = n0; }
    else if (n0 < 4096) { Wm = Wfl; Um = Ufl; st = 1024; nc0 = n0 - 3072; }
    else                { Wm = Wfr; Um = Ufr; st = 1024; nc0 = n0 - 4096; }
    const float* base = (k0 < 1024) ? Wm : Um;
    int kr0 = k0 & 1023;
    for (int e = threadIdx.x; e < 4096; e += 256) {
        int r = e >> 6, c = e & 63;
        ts[r][c] = base[(size_t)(kr0 + r) * st + nc0 + c];
    }
    __syncthreads();
    for (int u = threadIdx.x; u < 512; u += 256) {
        int nr = u >> 3, ko = u & 7;
        float f[8];
#pragma unroll
        for (int i = 0; i < 8; i++) f[i] = ts[ko * 8 + i][nr];
        size_t off = (size_t)(n0 + nr) * KTOT + k0 + ko * 8;
        *(uint4*)(g_Wh + off) = cvt8h(f);
    }
}

__global__ void pack_b_kernel(const float* __restrict__ bi,
                              const float* __restrict__ bfl,
                              const float* __restrict__ bfr) {
    int n = blockIdx.x * 256 + threadIdx.x;
    if (n >= NDIM) return;
    g_bcat[n] = (n < 3072) ? bi[n] : (n < 4096) ? bfl[n - 3072] : bfr[n - 4096];
}

// ---------------------------------------------------------------------------
// Embedding: write level-0 A rows (fp16).
// ---------------------------------------------------------------------------
__global__ __launch_bounds__(256)
void embed_kernel(const int* __restrict__ tokens, const float* __restrict__ emb) {
    int idx = blockIdx.x * 256 + threadIdx.x;
    if (idx >= Bd * 256 * 128) return;
    int u = idx & 127, t = idx >> 7;
    int b = t >> 8, l = t & 255;
    int tok = tokens[t];
    const float* s = emb + (size_t)tok * Hd + u * 8;
    float f[8];
    *(float4*)f       = *(const float4*)s;
    *(float4*)(f + 4) = *(const float4*)(s + 4);
    int r = b * 128 + (l >> 1);
    size_t off = (size_t)r * KTOT + (l & 1) * 1024 + u * 8;
    *(uint4*)(g_Ah + off) = cvt8h(f);
}

// ---------------------------------------------------------------------------
// HMMA GEMM, warp-specialized, templated N-tile (128 small levels / 256 big).
// CTA 128M x NT N. 8 consumer warps (4M x 2N, warp tile 32 x NT/2) + 2
// producer warps; mbarrier ring (5 stages NT=128, 3 stages NT=256).
// ---------------------------------------------------------------------------
template<int NT>
__global__ __launch_bounds__(320, 1)
void gemm_kernel(int level) {
    constexpr int NSTG = (NT == 128) ? 5 : 3;
    constexpr int SA = 128 * PITCH;
    constexpr int STB = (128 + NT) * PITCH;
    extern __shared__ char smraw[];
    const uint32_t smb = smem_u32(smraw);
    const uint32_t full0 = smb, empty0 = smb + 64;
    const uint32_t stg0 = smb + SMEM_BARS;
    const int tid = threadIdx.x, lane = tid & 31, wid = tid >> 5;
    const int M = Bd * (128 >> level);
    const int mt = blockIdx.x, bn = blockIdx.y;
    const size_t aRow0 = (size_t)(16384 - (16384 >> level)) + (size_t)mt * 128;
    const size_t bRow0 = (size_t)bn * NT;

    if (tid == 0) {
#pragma unroll
        for (int s = 0; s < NSTG; s++) {
            mbar_init(full0 + s * 8, 64);
            mbar_init(empty0 + s * 8, 8);
        }
        asm volatile("fence.proxy.async.shared::cta;" ::: "memory");
    }
    __syncthreads();

    if (wid >= 8) {
        // ---- producer: 2 warps, 64 threads ----
        const int ptid = tid - 256;
        const int lc = ptid & 7;
        const int lr = ptid >> 3;            // 0..7
        int stage = 0, phase = 1;
        for (int it = 0; it < 32; it++) {
            mbar_wait(empty0 + stage * 8, phase);
            uint32_t st = stg0 + stage * STB;
            int kb = it * 64;
#pragma unroll
            for (int i = 0; i < 16; i++) {           // A: 128 rows
                int row = lr + i * 8;
                cpasync16(st + row * PITCH + lc * 16,
                          g_Ah + (aRow0 + row) * KTOT + kb + lc * 8);
            }
#pragma unroll
            for (int i = 0; i < NT / 8; i++) {       // B: NT rows
                int row = lr + i * 8;
                cpasync16(st + SA + row * PITCH + lc * 16,
                          g_Wh + (bRow0 + row) * KTOT + kb + lc * 8);
            }
            cpasync_mbar_arrive(full0 + stage * 8);
            if (++stage == NSTG) { stage = 0; phase ^= 1; }
        }
        return;
    }

    // ---- consumers: 8 warps, 4M x 2N, warp tile 32 x NT/2 ----
    const int wm = wid >> 1, wn = wid & 1;
    constexpr int NB = NT / 16;      // acc n-tiles per warp (8 or 16)
    constexpr int NBP = NT / 32;     // b-frag ldsm per sub (4 or 8)

    float acc[2][NB][4];
#pragma unroll
    for (int a = 0; a < 2; a++)
#pragma unroll
        for (int b = 0; b < NB; b++)
#pragma unroll
            for (int c = 0; c < 4; c++) acc[a][b][c] = 0.0f;

    const uint32_t aB = stg0 + (wm * 32 + (lane & 15)) * PITCH + (lane >> 4) * 16;
    const uint32_t bB = stg0 + SA
                      + (wn * (NT / 2) + (lane & 7) + ((lane >> 4) << 3)) * PITCH
                      + ((lane >> 3) & 1) * 16;

    int stage = 0, phase = 0;
    for (int it = 0; it < 32; it++) {
        mbar_wait(full0 + stage * 8, phase);
        uint32_t sOff = (uint32_t)stage * STB;
#pragma unroll
        for (int sub = 0; sub < 4; sub++) {
            uint32_t aS = aB + sOff + sub * 32;
            uint32_t bS = bB + sOff + sub * 32;
            uint32_t av[2][4], bf[NBP][4];
            ldsm4(av[0], aS);
            ldsm4(av[1], aS + 16 * PITCH);
#pragma unroll
            for (int nbp = 0; nbp < NBP; nbp++)
                ldsm4(bf[nbp], bS + nbp * 16 * PITCH);
#pragma unroll
            for (int nbp = 0; nbp < NBP; nbp++)
#pragma unroll
                for (int mb = 0; mb < 2; mb++) {
                    mma16816(acc[mb][2*nbp],   av[mb], bf[nbp]);
                    mma16816(acc[mb][2*nbp+1], av[mb], bf[nbp] + 2);
                }
        }
        if (lane == 0) mbar_arrive(empty0 + stage * 8);
        if (++stage == NSTG) { stage = 0; phase ^= 1; }
    }

    // epilogue: fp16 stores (guarded for M=64 tail level)
    const int gm0 = mt * 128 + wm * 32;
    const int gn0 = bn * NT + wn * (NT / 2);
#pragma unroll
    for (int mb = 0; mb < 2; mb++) {
        int r0 = gm0 + mb * 16 + (lane >> 2);
#pragma unroll
        for (int nb = 0; nb < NB; nb++) {
            int cc = gn0 + nb * 8 + (lane & 3) * 2;
            if (r0 < M)
                *(uint32_t*)(g_pre + (size_t)r0 * NDIM + cc) =
                    pk2f(acc[mb][nb][0], acc[mb][nb][1]);
            if (r0 + 8 < M)
                *(uint32_t*)(g_pre + (size_t)(r0 + 8) * NDIM + cc) =
                    pk2f(acc[mb][nb][2], acc[mb][nb][3]);
        }
    }
}

// ---------------------------------------------------------------------------
// Gates: bias + LSTM gate math; fp16 g_pre and fp16 c ping-pong.
// ---------------------------------------------------------------------------
__global__ __launch_bounds__(256)
void gates_kernel(float* __restrict__ dout, int level) {
    const int P = 128 >> level;
    const int M = Bd * P;
    int idx = blockIdx.x * 256 + threadIdx.x;
    if (idx >= M * 128) return;
    int m = idx >> 7, u = idx & 127;
    int col0 = u << 3;

    const __half* prow = g_pre + (size_t)m * NDIM + col0;
    float pi[8], po[8], pk[8], pl[8], pr[8];
    ld8h(prow,        pi);
    ld8h(prow + 1024, po);
    ld8h(prow + 2048, pk);
    ld8h(prow + 3072, pl);
    ld8h(prow + 4096, pr);

    const float* bb = g_bcat + col0;
    float bi[8], bo[8], bk[8], bl[8], br[8];
    *(float4*)bi = *(const float4*)(bb);          *(float4*)(bi+4) = *(const float4*)(bb + 4);
    *(float4*)bo = *(const float4*)(bb + 1024);   *(float4*)(bo+4) = *(const float4*)(bb + 1028);
    *(float4*)bk = *(const float4*)(bb + 2048);   *(float4*)(bk+4) = *(const float4*)(bb + 2052);
    *(float4*)bl = *(const float4*)(bb + 3072);   *(float4*)(bl+4) = *(const float4*)(bb + 3076);
    *(float4*)br = *(const float4*)(bb + 4096);   *(float4*)(br+4) = *(const float4*)(bb + 4100);

    float cl[8] = {0,0,0,0,0,0,0,0}, cr[8] = {0,0,0,0,0,0,0,0};
    if (level > 0) {
        const __half* cp = g_cbuf[(level + 1) & 1] + (size_t)m * 2048 + col0;
        ld8h(cp,        cl);
        ld8h(cp + 1024, cr);
    }

    float cv[8], hv[8];
#pragma unroll
    for (int i = 0; i < 8; i++) {
        float c = sigf(pi[i] + bi[i]) * tanhf_(pk[i] + bk[i])
                + sigf(pl[i] + bl[i]) * cl[i]
                + sigf(pr[i] + br[i]) * cr[i];
        cv[i] = c;
        hv[i] = sigf(po[i] + bo[i]) * tanhf_(c);
    }

    *(uint4*)(g_cbuf[level & 1] + (size_t)m * Hd + col0) = cvt8h(cv);

    int b = m >> (7 - level);
    int j = m & (P - 1);
    int off = 256 - (256 >> level);
    float* hw = dout + ((size_t)b * FOREST + off + j) * Hd + col0;
    *(float4*)hw = *(const float4*)hv;  *(float4*)(hw + 4) = *(const float4*)(hv + 4);

    if (level < 7) {
        int r = b * (P >> 1) + (j >> 1);
        size_t rowbase = 16384 - (16384 >> (level + 1));
        size_t aoff = (rowbase + r) * (size_t)KTOT + (j & 1) * 1024 + col0;
        *(uint4*)(g_Ah + aoff) = cvt8h(hv);
    } else {
        float* hroot = dout + (size_t)Bd * FOREST * Hd + (size_t)m * Hd + col0;
        float* croot = hroot + (size_t)Bd * Hd;
        *(float4*)hroot = *(const float4*)hv;  *(float4*)(hroot + 4) = *(const float4*)(hv + 4);
        *(float4*)croot = *(const float4*)cv;  *(float4*)(croot + 4) = *(const float4*)(cv + 4);
    }
}

// ---------------------------------------------------------------------------
// launcher (graph-capturable: kernel launches only, default stream)
// ---------------------------------------------------------------------------
extern "C" void kernel_launch(void* const* d_in, const int* in_sizes, int n_in,
                              void* d_out, int out_size) {
    const int*   tokens = (const int*)  d_in[0];
    const float* emb    = (const float*)d_in[1];
    const float* W_iock = (const float*)d_in[2];
    const float* b_iock = (const float*)d_in[3];
    const float* U_iock = (const float*)d_in[4];
    const float* W_fl   = (const float*)d_in[5];
    const float* b_fl   = (const float*)d_in[6];
    const float* U_fl   = (const float*)d_in[7];
    const float* W_fr   = (const float*)d_in[8];
    const float* b_fr   = (const float*)d_in[9];
    const float* U_fr   = (const float*)d_in[10];
    float* out = (float*)d_out;

    const int SMEM128 = SMEM_BARS + 5 * (256 * PITCH);   // 185344
    const int SMEM256 = SMEM_BARS + 3 * (384 * PITCH);   // 166912

    static bool attr_set = false;
    if (!attr_set) {
        cudaFuncSetAttribute(gemm_kernel<128>, cudaFuncAttributeMaxDynamicSharedMemorySize, SMEM128);
        cudaFuncSetAttribute(gemm_kernel<256>, cudaFuncAttributeMaxDynamicSharedMemorySize, SMEM256);
        attr_set = true;
    }

    pack_w_kernel<<<dim3(32, 80), 256>>>(W_iock, U_iock, W_fl, U_fl, W_fr, U_fr);
    pack_b_kernel<<<20, 256>>>(b_iock, b_fl, b_fr);
    {
        int total = Bd * 256 * 128;
        embed_kernel<<<(total + 255) / 256, 256>>>(tokens, emb);
    }
    for (int level = 0; level < 8; ++level) {
        int M = Bd * (128 >> level);
        if (level < 2) {
            dim3 grid((M + 127) / 128, 20);
            gemm_kernel<256><<<grid, 320, SMEM256>>>(level);
        } else {
            dim3 grid((M + 127) / 128, 40);
            gemm_kernel<128><<<grid, 320, SMEM128>>>(level);
        }
        int units = M * 128;
        gates_kernel<<<(units + 255) / 256, 256>>>(out, level);
    }
}